// round 16
// baseline (speedup 1.0000x reference)
#include <cuda_runtime.h>
#include <cuda_bf16.h>
#include <cstdint>

#define B_SZ 16384
#define D_SZ 1024
#define HR_SZ 4096
#define OUT_SZ 10

// ---------------- scratch (static device arrays; no allocation) ----------------
__device__ __nv_bfloat16 g_x_hi[(size_t)B_SZ * D_SZ];
__device__ __nv_bfloat16 g_x_lo[(size_t)B_SZ * D_SZ];
__device__ __nv_bfloat16 g_i_hi[(size_t)B_SZ * HR_SZ];
__device__ __nv_bfloat16 g_i_lo[(size_t)B_SZ * HR_SZ];
__device__ __nv_bfloat16 g_wr1_hi[(size_t)HR_SZ * D_SZ], g_wr1_lo[(size_t)HR_SZ * D_SZ];
__device__ __nv_bfloat16 g_wl1_hi[(size_t)HR_SZ * D_SZ], g_wl1_lo[(size_t)HR_SZ * D_SZ];
__device__ __nv_bfloat16 g_we1_hi[(size_t)HR_SZ * D_SZ], g_we1_lo[(size_t)HR_SZ * D_SZ];
__device__ __nv_bfloat16 g_wr2_hi[(size_t)HR_SZ * D_SZ], g_wr2_lo[(size_t)HR_SZ * D_SZ];
__device__ __nv_bfloat16 g_wl2_hi[(size_t)HR_SZ * D_SZ], g_wl2_lo[(size_t)HR_SZ * D_SZ];
__device__ __nv_bfloat16 g_we2_hi[(size_t)HR_SZ * D_SZ], g_we2_lo[(size_t)HR_SZ * D_SZ];
__device__ float g_R[(size_t)B_SZ * HR_SZ];
__device__ float g_y[(size_t)B_SZ * D_SZ];
__device__ float g_h[(size_t)B_SZ * D_SZ];

// ---------------- helpers ----------------
__device__ __forceinline__ uint32_t smem_u32(const void* p) {
    uint32_t a;
    asm("{ .reg .u64 t; cvta.to.shared.u64 t, %1; cvt.u32.u64 %0, t; }" : "=r"(a) : "l"(p));
    return a;
}

__device__ __forceinline__ void cp16(uint32_t dst, const void* src) {
    asm volatile("cp.async.cg.shared.global [%0], [%1], 16;" :: "r"(dst), "l"(src));
}

#define CP_COMMIT() asm volatile("cp.async.commit_group;" ::: "memory")
#define CP_WAIT0()  asm volatile("cp.async.wait_group 0;" ::: "memory")

#define LDSM4(R0, R1, R2, R3, A)                                                   \
    asm volatile("ldmatrix.sync.aligned.m8n8.x4.shared.b16 {%0,%1,%2,%3}, [%4];"   \
                 : "=r"(R0), "=r"(R1), "=r"(R2), "=r"(R3) : "r"(A))

__device__ __forceinline__ void mma16816(float* c, const uint32_t* a, const uint32_t* b) {
    asm volatile(
        "mma.sync.aligned.m16n8k16.row.col.f32.bf16.bf16.f32 "
        "{%0,%1,%2,%3}, {%4,%5,%6,%7}, {%8,%9}, {%0,%1,%2,%3};"
        : "+f"(c[0]), "+f"(c[1]), "+f"(c[2]), "+f"(c[3])
        : "r"(a[0]), "r"(a[1]), "r"(a[2]), "r"(a[3]), "r"(b[0]), "r"(b[1]));
}

__device__ __forceinline__ void split4(const float* in, __nv_bfloat16* hi,
                                       __nv_bfloat16* lo, size_t i) {
    float4 v = *(const float4*)(in + i);
    float a[4] = {v.x, v.y, v.z, v.w};
    __nv_bfloat16 h[4], l[4];
#pragma unroll
    for (int j = 0; j < 4; j++) {
        h[j] = __float2bfloat16(a[j]);
        l[j] = __float2bfloat16(a[j] - __bfloat162float(h[j]));
    }
    __nv_bfloat162 h0; h0.x = h[0]; h0.y = h[1];
    __nv_bfloat162 h1; h1.x = h[2]; h1.y = h[3];
    __nv_bfloat162 l0; l0.x = l[0]; l0.y = l[1];
    __nv_bfloat162 l1; l1.x = l[2]; l1.y = l[3];
    ((__nv_bfloat162*)(hi + i))[0] = h0;
    ((__nv_bfloat162*)(hi + i))[1] = h1;
    ((__nv_bfloat162*)(lo + i))[0] = l0;
    ((__nv_bfloat162*)(lo + i))[1] = l1;
}

// ---------------- megasplit: x (16384 blocks) + 6 weights (4096 blocks each) ----------------
__global__ void megasplit_kernel(
    const float* __restrict__ x,
    const float* __restrict__ w0, const float* __restrict__ w1, const float* __restrict__ w2,
    const float* __restrict__ w3, const float* __restrict__ w4, const float* __restrict__ w5,
    __nv_bfloat16* __restrict__ xh, __nv_bfloat16* __restrict__ xl,
    __nv_bfloat16* __restrict__ h0, __nv_bfloat16* __restrict__ l0,
    __nv_bfloat16* __restrict__ h1, __nv_bfloat16* __restrict__ l1,
    __nv_bfloat16* __restrict__ h2, __nv_bfloat16* __restrict__ l2,
    __nv_bfloat16* __restrict__ h3, __nv_bfloat16* __restrict__ l3,
    __nv_bfloat16* __restrict__ h4, __nv_bfloat16* __restrict__ l4,
    __nv_bfloat16* __restrict__ h5, __nv_bfloat16* __restrict__ l5) {
    const int b = blockIdx.x;
    const float* in;
    __nv_bfloat16 *hi, *lo;
    size_t base;
    if (b < 16384) {
        in = x; hi = xh; lo = xl; base = (size_t)b * 1024;
    } else {
        const int t = b - 16384;
        const int wi = t >> 12;
        base = (size_t)(t & 4095) * 1024;
        switch (wi) {
            case 0: in = w0; hi = h0; lo = l0; break;
            case 1: in = w1; hi = h1; lo = l1; break;
            case 2: in = w2; hi = h2; lo = l2; break;
            case 3: in = w3; hi = h3; lo = l3; break;
            case 4: in = w4; hi = h4; lo = l4; break;
            default: in = w5; hi = h5; lo = l5; break;
        }
    }
    split4(in, hi, lo, base + (size_t)threadIdx.x * 4);
}

// ---------------- split-bf16 mma.sync GEMM: C = A * B^T (+bias) (op extra) ----------------
// CTA tile 128x64, warp tile 32x32 (8 warps, 4x2), K-chunk 64, 2-stage cp.async,
// single barrier per chunk (fill(kc+1) issued after the barrier, in compute shadow).
// 2 CTAs/SM: 96KB smem/CTA, <=128 regs/thread via __launch_bounds__(256, 2).
// EPI: 0 = +bias -> C fp32; 2 = (+bias)+extra -> C fp32; 3 = (+bias)*extra -> bf16 hi/lo
#define STAGE_B 49152
#define SMEM_TOTAL 98304
#define OFF_AH 0
#define OFF_AL 16384
#define OFF_BH 32768
#define OFF_BL 40960

template <int EPI>
__global__ void __launch_bounds__(256, 2)
gemm_mma(const __nv_bfloat16* __restrict__ Ahi, const __nv_bfloat16* __restrict__ Alo,
         const __nv_bfloat16* __restrict__ Bhi, const __nv_bfloat16* __restrict__ Blo,
         const float* __restrict__ bias, const float* __restrict__ extra,
         float* __restrict__ C, __nv_bfloat16* __restrict__ Chi,
         __nv_bfloat16* __restrict__ Clo, int M, int N, int K) {
    extern __shared__ char smem[];
    const uint32_t sb = smem_u32(smem);
    const int tid = threadIdx.x;
    const int wid = tid >> 5;
    const int lane = tid & 31;
    const int warp_m = wid & 3;
    const int warp_n = wid >> 2;
    const int bm = blockIdx.y * 128;
    const int bn = blockIdx.x * 64;

    const int rowA_l = (lane & 15);
    const int ca = lane >> 4;
    const int rowB_l = (lane & 7) + ((lane & 16) >> 1);
    const int cb = (lane >> 3) & 1;

    float acc[2][4][4];
#pragma unroll
    for (int i = 0; i < 2; i++)
#pragma unroll
        for (int j = 0; j < 4; j++)
#pragma unroll
            for (int q = 0; q < 4; q++) acc[i][j][q] = 0.f;

    const int nk = K >> 6;

#define FILL_STAGE(stg, kc_)                                                            \
    {                                                                                   \
        const int k0_ = (kc_) << 6;                                                     \
        const uint32_t sbase = sb + (stg) * STAGE_B;                                    \
        _Pragma("unroll")                                                               \
        for (int i = tid; i < 1024; i += 256) {                                         \
            const int r = i >> 3;                                                       \
            const int g = i & 7;                                                        \
            const uint32_t so = (uint32_t)(r * 128 + ((g ^ (r & 7)) << 4));             \
            const size_t ga = (size_t)(bm + r) * K + k0_ + g * 8;                       \
            cp16(sbase + OFF_AH + so, Ahi + ga);                                        \
            cp16(sbase + OFF_AL + so, Alo + ga);                                        \
        }                                                                               \
        _Pragma("unroll")                                                               \
        for (int i = tid; i < 512; i += 256) {                                          \
            const int r = i >> 3;                                                       \
            const int g = i & 7;                                                        \
            const uint32_t so = (uint32_t)(r * 128 + ((g ^ (r & 7)) << 4));             \
            const size_t gb = (size_t)(bn + r) * K + k0_ + g * 8;                       \
            cp16(sbase + OFF_BH + so, Bhi + gb);                                        \
            cp16(sbase + OFF_BL + so, Blo + gb);                                        \
        }                                                                               \
    }

    FILL_STAGE(0, 0);
    CP_COMMIT();

    for (int kc = 0; kc < nk; kc++) {
        // fill(kc) complete (own thread), then barrier makes all threads' fills visible
        CP_WAIT0();
        __syncthreads();
        // refill the other stage in the shadow of this chunk's compute.
        // WAR-safe: the barrier above proves every warp finished reading stage
        // (kc+1)&1 during chunk kc-1.
        if (kc + 1 < nk) {
            FILL_STAGE((kc + 1) & 1, kc + 1);
            CP_COMMIT();
        }

        const uint32_t sbase = sb + (kc & 1) * STAGE_B;
#pragma unroll
        for (int s = 0; s < 4; s++) {
            uint32_t ah[2][4], al[2][4];
#pragma unroll
            for (int mt = 0; mt < 2; mt++) {
                const int rA = warp_m * 32 + mt * 16 + rowA_l;
                const uint32_t off = (uint32_t)(rA * 128 + (((2 * s + ca) ^ (rA & 7)) << 4));
                LDSM4(ah[mt][0], ah[mt][1], ah[mt][2], ah[mt][3], sbase + OFF_AH + off);
                LDSM4(al[mt][0], al[mt][1], al[mt][2], al[mt][3], sbase + OFF_AL + off);
            }
            uint32_t bh[4][2], bl[4][2];
#pragma unroll
            for (int ntp = 0; ntp < 2; ntp++) {
                const int rB = warp_n * 32 + ntp * 16 + rowB_l;
                const uint32_t off = (uint32_t)(rB * 128 + (((2 * s + cb) ^ (rB & 7)) << 4));
                uint32_t r0, r1, r2, r3;
                LDSM4(r0, r1, r2, r3, sbase + OFF_BH + off);
                bh[ntp * 2][0] = r0; bh[ntp * 2][1] = r1;
                bh[ntp * 2 + 1][0] = r2; bh[ntp * 2 + 1][1] = r3;
                LDSM4(r0, r1, r2, r3, sbase + OFF_BL + off);
                bl[ntp * 2][0] = r0; bl[ntp * 2][1] = r1;
                bl[ntp * 2 + 1][0] = r2; bl[ntp * 2 + 1][1] = r3;
            }
#pragma unroll
            for (int mt = 0; mt < 2; mt++)
#pragma unroll
                for (int nt = 0; nt < 4; nt++) {
                    mma16816(acc[mt][nt], ah[mt], bh[nt]);
                    mma16816(acc[mt][nt], ah[mt], bl[nt]);
                    mma16816(acc[mt][nt], al[mt], bh[nt]);
                }
        }
    }

    // ---- epilogue ----
    const int row0 = bm + warp_m * 32 + (lane >> 2);
    const int col0 = bn + warp_n * 32 + (lane & 3) * 2;
#pragma unroll
    for (int mt = 0; mt < 2; mt++) {
#pragma unroll
        for (int nt = 0; nt < 4; nt++) {
            const int c = col0 + nt * 8;
            const float b0 = bias[c], b1 = bias[c + 1];
#pragma unroll
            for (int half = 0; half < 2; half++) {
                const int r = row0 + mt * 16 + half * 8;
                const size_t o = (size_t)r * N + c;
                float v0 = acc[mt][nt][half * 2 + 0] + b0;
                float v1 = acc[mt][nt][half * 2 + 1] + b1;
                if (EPI == 2) {
                    float2 e = *(const float2*)(extra + o);
                    v0 += e.x; v1 += e.y;
                }
                if (EPI == 3) {
                    float2 e = *(const float2*)(extra + o);
                    v0 *= e.x; v1 *= e.y;
                    __nv_bfloat162 h2, l2;
                    h2.x = __float2bfloat16(v0);
                    h2.y = __float2bfloat16(v1);
                    l2.x = __float2bfloat16(v0 - __bfloat162float(h2.x));
                    l2.y = __float2bfloat16(v1 - __bfloat162float(h2.y));
                    *(__nv_bfloat162*)(Chi + o) = h2;
                    *(__nv_bfloat162*)(Clo + o) = l2;
                } else {
                    float2 out2; out2.x = v0; out2.y = v1;
                    *(float2*)(C + o) = out2;
                }
            }
        }
    }
}

// ---------------- LayerNorm over rows of 1024; optionally also emits bf16 hi/lo split ----------------
template <int DO_SPLIT>
__global__ void ln_kernel(const float* __restrict__ y, const float* __restrict__ g,
                          const float* __restrict__ b, float* __restrict__ h,
                          __nv_bfloat16* __restrict__ hhi, __nv_bfloat16* __restrict__ hlo) {
    __shared__ float red[256];
    const int row = blockIdx.x;
    const int t = threadIdx.x;
    const float* yr = y + (size_t)row * 1024;
    float v[4];
    float s = 0.f;
#pragma unroll
    for (int i = 0; i < 4; i++) {
        v[i] = yr[t + i * 256];
        s += v[i];
    }
    red[t] = s;
    __syncthreads();
#pragma unroll
    for (int o = 128; o > 0; o >>= 1) {
        if (t < o) red[t] += red[t + o];
        __syncthreads();
    }
    const float mu = red[0] * (1.f / 1024.f);
    __syncthreads();
    float q = 0.f;
#pragma unroll
    for (int i = 0; i < 4; i++) {
        float d = v[i] - mu;
        q += d * d;
    }
    red[t] = q;
    __syncthreads();
#pragma unroll
    for (int o = 128; o > 0; o >>= 1) {
        if (t < o) red[t] += red[t + o];
        __syncthreads();
    }
    const float rstd = rsqrtf(red[0] * (1.f / 1024.f) + 1e-5f);
    float* hr = h + (size_t)row * 1024;
#pragma unroll
    for (int i = 0; i < 4; i++) {
        const int c = t + i * 256;
        const float hv = (v[i] - mu) * rstd * g[c] + b[c];
        hr[c] = hv;
        if (DO_SPLIT) {
            const size_t o = (size_t)row * 1024 + c;
            __nv_bfloat16 hb = __float2bfloat16(hv);
            hhi[o] = hb;
            hlo[o] = __float2bfloat16(hv - __bfloat162float(hb));
        }
    }
}

// ---------------- head: out[B,10] = h @ wf^T + bf ----------------
__global__ void head_kernel(const float* __restrict__ h, const float* __restrict__ wf,
                            const float* __restrict__ bf, float* __restrict__ out) {
    __shared__ float sh[1024];
    const int row = blockIdx.x;
    const int t = threadIdx.x;
    const float* hr = h + (size_t)row * 1024;
    for (int i = t; i < 1024; i += 256) sh[i] = hr[i];
    __syncthreads();
    const int w = t >> 5;
    const int lane = t & 31;
    for (int j = w; j < OUT_SZ; j += 8) {
        const float* wr = wf + (size_t)j * 1024;
        float s = 0.f;
#pragma unroll 8
        for (int d = lane; d < 1024; d += 32) s += sh[d] * wr[d];
#pragma unroll
        for (int o = 16; o > 0; o >>= 1) s += __shfl_xor_sync(0xffffffffu, s, o);
        if (lane == 0) out[(size_t)row * OUT_SZ + j] = s + bf[j];
    }
}

// ---------------- host orchestration ----------------
struct Bufs {
    __nv_bfloat16 *x_hi, *x_lo, *i_hi, *i_lo;
    float *R, *y, *h;
};

template <int LN_SPLIT>
static void run_block(const float* xin, const __nv_bfloat16* wr_hi, const __nv_bfloat16* wr_lo,
                      const float* br, const __nv_bfloat16* wl_hi, const __nv_bfloat16* wl_lo,
                      const float* bl, const __nv_bfloat16* we_hi, const __nv_bfloat16* we_lo,
                      const float* be, const float* g, const float* b, const Bufs& u) {
    gemm_mma<0><<<dim3(HR_SZ / 64, B_SZ / 128), 256, SMEM_TOTAL>>>(
        u.x_hi, u.x_lo, wr_hi, wr_lo, br, nullptr, u.R, nullptr, nullptr, B_SZ, HR_SZ, D_SZ);
    gemm_mma<3><<<dim3(HR_SZ / 64, B_SZ / 128), 256, SMEM_TOTAL>>>(
        u.x_hi, u.x_lo, wl_hi, wl_lo, bl, u.R, nullptr, u.i_hi, u.i_lo, B_SZ, HR_SZ, D_SZ);
    gemm_mma<2><<<dim3(D_SZ / 64, B_SZ / 128), 256, SMEM_TOTAL>>>(
        u.i_hi, u.i_lo, we_hi, we_lo, be, xin, u.y, nullptr, nullptr, B_SZ, D_SZ, HR_SZ);
    // h = LN(y)*g + b; block 1 also writes the split for block 2's A operand
    ln_kernel<LN_SPLIT><<<B_SZ, 256>>>(u.y, g, b, u.h, u.x_hi, u.x_lo);
}

extern "C" void kernel_launch(void* const* d_in, const int* in_sizes, int n_in, void* d_out,
                              int out_size) {
    (void)in_sizes; (void)n_in; (void)out_size;
    const float* x   = (const float*)d_in[0];
    const float* wr1 = (const float*)d_in[1];
    const float* br1 = (const float*)d_in[2];
    const float* wl1 = (const float*)d_in[3];
    const float* bl1 = (const float*)d_in[4];
    const float* we1 = (const float*)d_in[5];
    const float* be1 = (const float*)d_in[6];
    const float* g1  = (const float*)d_in[7];
    const float* b1  = (const float*)d_in[8];
    const float* wr2 = (const float*)d_in[9];
    const float* br2 = (const float*)d_in[10];
    const float* wl2 = (const float*)d_in[11];
    const float* bl2 = (const float*)d_in[12];
    const float* we2 = (const float*)d_in[13];
    const float* be2 = (const float*)d_in[14];
    const float* g2  = (const float*)d_in[15];
    const float* b2  = (const float*)d_in[16];
    const float* wf  = (const float*)d_in[17];
    const float* bf  = (const float*)d_in[18];
    float* out = (float*)d_out;

    void* pv;
    Bufs u;
    cudaGetSymbolAddress(&pv, g_x_hi); u.x_hi = (__nv_bfloat16*)pv;
    cudaGetSymbolAddress(&pv, g_x_lo); u.x_lo = (__nv_bfloat16*)pv;
    cudaGetSymbolAddress(&pv, g_i_hi); u.i_hi = (__nv_bfloat16*)pv;
    cudaGetSymbolAddress(&pv, g_i_lo); u.i_lo = (__nv_bfloat16*)pv;
    cudaGetSymbolAddress(&pv, g_R);    u.R = (float*)pv;
    cudaGetSymbolAddress(&pv, g_y);    u.y = (float*)pv;
    cudaGetSymbolAddress(&pv, g_h);    u.h = (float*)pv;

    __nv_bfloat16 *wr1h, *wr1l, *wl1h, *wl1l, *we1h, *we1l;
    __nv_bfloat16 *wr2h, *wr2l, *wl2h, *wl2l, *we2h, *we2l;
    cudaGetSymbolAddress(&pv, g_wr1_hi); wr1h = (__nv_bfloat16*)pv;
    cudaGetSymbolAddress(&pv, g_wr1_lo); wr1l = (__nv_bfloat16*)pv;
    cudaGetSymbolAddress(&pv, g_wl1_hi); wl1h = (__nv_bfloat16*)pv;
    cudaGetSymbolAddress(&pv, g_wl1_lo); wl1l = (__nv_bfloat16*)pv;
    cudaGetSymbolAddress(&pv, g_we1_hi); we1h = (__nv_bfloat16*)pv;
    cudaGetSymbolAddress(&pv, g_we1_lo); we1l = (__nv_bfloat16*)pv;
    cudaGetSymbolAddress(&pv, g_wr2_hi); wr2h = (__nv_bfloat16*)pv;
    cudaGetSymbolAddress(&pv, g_wr2_lo); wr2l = (__nv_bfloat16*)pv;
    cudaGetSymbolAddress(&pv, g_wl2_hi); wl2h = (__nv_bfloat16*)pv;
    cudaGetSymbolAddress(&pv, g_wl2_lo); wl2l = (__nv_bfloat16*)pv;
    cudaGetSymbolAddress(&pv, g_we2_hi); we2h = (__nv_bfloat16*)pv;
    cudaGetSymbolAddress(&pv, g_we2_lo); we2l = (__nv_bfloat16*)pv;

    cudaFuncSetAttribute(gemm_mma<0>, cudaFuncAttributeMaxDynamicSharedMemorySize, SMEM_TOTAL);
    cudaFuncSetAttribute(gemm_mma<2>, cudaFuncAttributeMaxDynamicSharedMemorySize, SMEM_TOTAL);
    cudaFuncSetAttribute(gemm_mma<3>, cudaFuncAttributeMaxDynamicSharedMemorySize, SMEM_TOTAL);

    // idx 0 = megasplit, idx 1..3 = GEMMs (ncu -s 5 lands on a GEMM for any 2-4 launch prefix).
    megasplit_kernel<<<B_SZ + 6 * (HR_SZ * D_SZ / 1024), 256>>>(
        x, wr1, wl1, we1, wr2, wl2, we2,
        u.x_hi, u.x_lo, wr1h, wr1l, wl1h, wl1l, we1h, we1l,
        wr2h, wr2l, wl2h, wl2l, we2h, we2l);                                     // 0

    run_block<1>(x, wr1h, wr1l, br1, wl1h, wl1l, bl1, we1h, we1l, be1, g1, b1, u);  // 1..4 (ln writes split)

    run_block<0>(u.h, wr2h, wr2l, br2, wl2h, wl2l, bl2, we2h, we2l, be2, g2, b2, u); // 5..8

    head_kernel<<<B_SZ, 256>>>(u.h, wf, bf, out);                                    // 9
}

// round 17
// speedup vs baseline: 1.0377x; 1.0377x over previous
#include <cuda_runtime.h>
#include <cuda_bf16.h>
#include <cstdint>

#define B_SZ 16384
#define D_SZ 1024
#define HR_SZ 4096
#define OUT_SZ 10

// ---------------- scratch (static device arrays; no allocation) ----------------
__device__ __nv_bfloat16 g_x_hi[(size_t)B_SZ * D_SZ];
__device__ __nv_bfloat16 g_x_lo[(size_t)B_SZ * D_SZ];
__device__ __nv_bfloat16 g_i_hi[(size_t)B_SZ * HR_SZ];
__device__ __nv_bfloat16 g_i_lo[(size_t)B_SZ * HR_SZ];
__device__ __nv_bfloat16 g_wr1_hi[(size_t)HR_SZ * D_SZ], g_wr1_lo[(size_t)HR_SZ * D_SZ];
__device__ __nv_bfloat16 g_wl1_hi[(size_t)HR_SZ * D_SZ], g_wl1_lo[(size_t)HR_SZ * D_SZ];
__device__ __nv_bfloat16 g_we1_hi[(size_t)HR_SZ * D_SZ], g_we1_lo[(size_t)HR_SZ * D_SZ];
__device__ __nv_bfloat16 g_wr2_hi[(size_t)HR_SZ * D_SZ], g_wr2_lo[(size_t)HR_SZ * D_SZ];
__device__ __nv_bfloat16 g_wl2_hi[(size_t)HR_SZ * D_SZ], g_wl2_lo[(size_t)HR_SZ * D_SZ];
__device__ __nv_bfloat16 g_we2_hi[(size_t)HR_SZ * D_SZ], g_we2_lo[(size_t)HR_SZ * D_SZ];
__device__ float g_R[(size_t)B_SZ * HR_SZ];
__device__ float g_y[(size_t)B_SZ * D_SZ];
__device__ float g_h[(size_t)B_SZ * D_SZ];

// ---------------- helpers ----------------
__device__ __forceinline__ uint32_t smem_u32(const void* p) {
    uint32_t a;
    asm("{ .reg .u64 t; cvta.to.shared.u64 t, %1; cvt.u32.u64 %0, t; }" : "=r"(a) : "l"(p));
    return a;
}

__device__ __forceinline__ void cp16(uint32_t dst, const void* src) {
    asm volatile("cp.async.cg.shared.global [%0], [%1], 16;" :: "r"(dst), "l"(src));
}

#define CP_COMMIT() asm volatile("cp.async.commit_group;" ::: "memory")
#define CP_WAIT1()  asm volatile("cp.async.wait_group 1;" ::: "memory")
#define CP_WAIT0()  asm volatile("cp.async.wait_group 0;" ::: "memory")

#define LDSM4(R0, R1, R2, R3, A)                                                   \
    asm volatile("ldmatrix.sync.aligned.m8n8.x4.shared.b16 {%0,%1,%2,%3}, [%4];"   \
                 : "=r"(R0), "=r"(R1), "=r"(R2), "=r"(R3) : "r"(A))

__device__ __forceinline__ void mma16816(float* c, const uint32_t* a, const uint32_t* b) {
    asm volatile(
        "mma.sync.aligned.m16n8k16.row.col.f32.bf16.bf16.f32 "
        "{%0,%1,%2,%3}, {%4,%5,%6,%7}, {%8,%9}, {%0,%1,%2,%3};"
        : "+f"(c[0]), "+f"(c[1]), "+f"(c[2]), "+f"(c[3])
        : "r"(a[0]), "r"(a[1]), "r"(a[2]), "r"(a[3]), "r"(b[0]), "r"(b[1]));
}

__device__ __forceinline__ void split4(const float* in, __nv_bfloat16* hi,
                                       __nv_bfloat16* lo, size_t i) {
    float4 v = *(const float4*)(in + i);
    float a[4] = {v.x, v.y, v.z, v.w};
    __nv_bfloat16 h[4], l[4];
#pragma unroll
    for (int j = 0; j < 4; j++) {
        h[j] = __float2bfloat16(a[j]);
        l[j] = __float2bfloat16(a[j] - __bfloat162float(h[j]));
    }
    __nv_bfloat162 h0; h0.x = h[0]; h0.y = h[1];
    __nv_bfloat162 h1; h1.x = h[2]; h1.y = h[3];
    __nv_bfloat162 l0; l0.x = l[0]; l0.y = l[1];
    __nv_bfloat162 l1; l1.x = l[2]; l1.y = l[3];
    ((__nv_bfloat162*)(hi + i))[0] = h0;
    ((__nv_bfloat162*)(hi + i))[1] = h1;
    ((__nv_bfloat162*)(lo + i))[0] = l0;
    ((__nv_bfloat162*)(lo + i))[1] = l1;
}

// ---------------- megasplit: x (16384 blocks) + 6 weights (4096 blocks each) ----------------
__global__ void megasplit_kernel(
    const float* __restrict__ x,
    const float* __restrict__ w0, const float* __restrict__ w1, const float* __restrict__ w2,
    const float* __restrict__ w3, const float* __restrict__ w4, const float* __restrict__ w5,
    __nv_bfloat16* __restrict__ xh, __nv_bfloat16* __restrict__ xl,
    __nv_bfloat16* __restrict__ h0, __nv_bfloat16* __restrict__ l0,
    __nv_bfloat16* __restrict__ h1, __nv_bfloat16* __restrict__ l1,
    __nv_bfloat16* __restrict__ h2, __nv_bfloat16* __restrict__ l2,
    __nv_bfloat16* __restrict__ h3, __nv_bfloat16* __restrict__ l3,
    __nv_bfloat16* __restrict__ h4, __nv_bfloat16* __restrict__ l4,
    __nv_bfloat16* __restrict__ h5, __nv_bfloat16* __restrict__ l5) {
    const int b = blockIdx.x;
    const float* in;
    __nv_bfloat16 *hi, *lo;
    size_t base;
    if (b < 16384) {
        in = x; hi = xh; lo = xl; base = (size_t)b * 1024;
    } else {
        const int t = b - 16384;
        const int wi = t >> 12;
        base = (size_t)(t & 4095) * 1024;
        switch (wi) {
            case 0: in = w0; hi = h0; lo = l0; break;
            case 1: in = w1; hi = h1; lo = l1; break;
            case 2: in = w2; hi = h2; lo = l2; break;
            case 3: in = w3; hi = h3; lo = l3; break;
            case 4: in = w4; hi = h4; lo = l4; break;
            default: in = w5; hi = h5; lo = l5; break;
        }
    }
    split4(in, hi, lo, base + (size_t)threadIdx.x * 4);
}

// ---------------- split-bf16 mma.sync GEMM: C = A * B^T (+bias) (op extra) ----------------
// CTA tile 128x64, warp tile 32x32 (8 warps, 4x2), K-chunk 64, 2-stage cp.async
// with the R15 schedule: FILL(kc+1); COMMIT; WAIT1; sync; compute; sync.
// 2 CTAs/SM: 96KB smem/CTA, <=128 regs/thread via __launch_bounds__(256, 2).
// EPI: 0 = +bias -> C fp32; 2 = (+bias)+extra -> C fp32; 3 = (+bias)*extra -> bf16 hi/lo
#define STAGE_B 49152
#define SMEM_TOTAL 98304
#define OFF_AH 0
#define OFF_AL 16384
#define OFF_BH 32768
#define OFF_BL 40960

template <int EPI>
__global__ void __launch_bounds__(256, 2)
gemm_mma(const __nv_bfloat16* __restrict__ Ahi, const __nv_bfloat16* __restrict__ Alo,
         const __nv_bfloat16* __restrict__ Bhi, const __nv_bfloat16* __restrict__ Blo,
         const float* __restrict__ bias, const float* __restrict__ extra,
         float* __restrict__ C, __nv_bfloat16* __restrict__ Chi,
         __nv_bfloat16* __restrict__ Clo, int M, int N, int K) {
    extern __shared__ char smem[];
    const uint32_t sb = smem_u32(smem);
    const int tid = threadIdx.x;
    const int wid = tid >> 5;
    const int lane = tid & 31;
    const int warp_m = wid & 3;
    const int warp_n = wid >> 2;
    const int bm = blockIdx.y * 128;
    const int bn = blockIdx.x * 64;

    const int rowA_l = (lane & 15);
    const int ca = lane >> 4;
    const int rowB_l = (lane & 7) + ((lane & 16) >> 1);
    const int cb = (lane >> 3) & 1;

    float acc[2][4][4];
#pragma unroll
    for (int i = 0; i < 2; i++)
#pragma unroll
        for (int j = 0; j < 4; j++)
#pragma unroll
            for (int q = 0; q < 4; q++) acc[i][j][q] = 0.f;

    const int nk = K >> 6;

#define FILL_STAGE(stg, kc_)                                                            \
    {                                                                                   \
        const int k0_ = (kc_) << 6;                                                     \
        const uint32_t sbase = sb + (stg) * STAGE_B;                                    \
        _Pragma("unroll")                                                               \
        for (int i = tid; i < 1024; i += 256) {                                         \
            const int r = i >> 3;                                                       \
            const int g = i & 7;                                                        \
            const uint32_t so = (uint32_t)(r * 128 + ((g ^ (r & 7)) << 4));             \
            const size_t ga = (size_t)(bm + r) * K + k0_ + g * 8;                       \
            cp16(sbase + OFF_AH + so, Ahi + ga);                                        \
            cp16(sbase + OFF_AL + so, Alo + ga);                                        \
        }                                                                               \
        _Pragma("unroll")                                                               \
        for (int i = tid; i < 512; i += 256) {                                          \
            const int r = i >> 3;                                                       \
            const int g = i & 7;                                                        \
            const uint32_t so = (uint32_t)(r * 128 + ((g ^ (r & 7)) << 4));             \
            const size_t gb = (size_t)(bn + r) * K + k0_ + g * 8;                       \
            cp16(sbase + OFF_BH + so, Bhi + gb);                                        \
            cp16(sbase + OFF_BL + so, Blo + gb);                                        \
        }                                                                               \
    }

    FILL_STAGE(0, 0);
    CP_COMMIT();

    for (int kc = 0; kc < nk; kc++) {
        if (kc + 1 < nk) {
            FILL_STAGE((kc + 1) & 1, kc + 1);
            CP_COMMIT();
            CP_WAIT1();
        } else {
            CP_WAIT0();
        }
        __syncthreads();

        const uint32_t sbase = sb + (kc & 1) * STAGE_B;
#pragma unroll
        for (int s = 0; s < 4; s++) {
            uint32_t ah[2][4], al[2][4];
#pragma unroll
            for (int mt = 0; mt < 2; mt++) {
                const int rA = warp_m * 32 + mt * 16 + rowA_l;
                const uint32_t off = (uint32_t)(rA * 128 + (((2 * s + ca) ^ (rA & 7)) << 4));
                LDSM4(ah[mt][0], ah[mt][1], ah[mt][2], ah[mt][3], sbase + OFF_AH + off);
                LDSM4(al[mt][0], al[mt][1], al[mt][2], al[mt][3], sbase + OFF_AL + off);
            }
            uint32_t bh[4][2], bl[4][2];
#pragma unroll
            for (int ntp = 0; ntp < 2; ntp++) {
                const int rB = warp_n * 32 + ntp * 16 + rowB_l;
                const uint32_t off = (uint32_t)(rB * 128 + (((2 * s + cb) ^ (rB & 7)) << 4));
                uint32_t r0, r1, r2, r3;
                LDSM4(r0, r1, r2, r3, sbase + OFF_BH + off);
                bh[ntp * 2][0] = r0; bh[ntp * 2][1] = r1;
                bh[ntp * 2 + 1][0] = r2; bh[ntp * 2 + 1][1] = r3;
                LDSM4(r0, r1, r2, r3, sbase + OFF_BL + off);
                bl[ntp * 2][0] = r0; bl[ntp * 2][1] = r1;
                bl[ntp * 2 + 1][0] = r2; bl[ntp * 2 + 1][1] = r3;
            }
#pragma unroll
            for (int mt = 0; mt < 2; mt++)
#pragma unroll
                for (int nt = 0; nt < 4; nt++) {
                    mma16816(acc[mt][nt], ah[mt], bh[nt]);
                    mma16816(acc[mt][nt], ah[mt], bl[nt]);
                    mma16816(acc[mt][nt], al[mt], bh[nt]);
                }
        }
        __syncthreads();
    }

    // ---- epilogue ----
    const int row0 = bm + warp_m * 32 + (lane >> 2);
    const int col0 = bn + warp_n * 32 + (lane & 3) * 2;
#pragma unroll
    for (int mt = 0; mt < 2; mt++) {
#pragma unroll
        for (int nt = 0; nt < 4; nt++) {
            const int c = col0 + nt * 8;
            const float b0 = bias[c], b1 = bias[c + 1];
#pragma unroll
            for (int half = 0; half < 2; half++) {
                const int r = row0 + mt * 16 + half * 8;
                const size_t o = (size_t)r * N + c;
                float v0 = acc[mt][nt][half * 2 + 0] + b0;
                float v1 = acc[mt][nt][half * 2 + 1] + b1;
                if (EPI == 2) {
                    float2 e = *(const float2*)(extra + o);
                    v0 += e.x; v1 += e.y;
                }
                if (EPI == 3) {
                    float2 e = *(const float2*)(extra + o);
                    v0 *= e.x; v1 *= e.y;
                    __nv_bfloat162 h2, l2;
                    h2.x = __float2bfloat16(v0);
                    h2.y = __float2bfloat16(v1);
                    l2.x = __float2bfloat16(v0 - __bfloat162float(h2.x));
                    l2.y = __float2bfloat16(v1 - __bfloat162float(h2.y));
                    *(__nv_bfloat162*)(Chi + o) = h2;
                    *(__nv_bfloat162*)(Clo + o) = l2;
                } else {
                    float2 out2; out2.x = v0; out2.y = v1;
                    *(float2*)(C + o) = out2;
                }
            }
        }
    }
}

// ---------------- LayerNorm over rows of 1024; optionally also emits bf16 hi/lo split ----------------
template <int DO_SPLIT>
__global__ void ln_kernel(const float* __restrict__ y, const float* __restrict__ g,
                          const float* __restrict__ b, float* __restrict__ h,
                          __nv_bfloat16* __restrict__ hhi, __nv_bfloat16* __restrict__ hlo) {
    __shared__ float red[256];
    const int row = blockIdx.x;
    const int t = threadIdx.x;
    const float* yr = y + (size_t)row * 1024;
    float v[4];
    float s = 0.f;
#pragma unroll
    for (int i = 0; i < 4; i++) {
        v[i] = yr[t + i * 256];
        s += v[i];
    }
    red[t] = s;
    __syncthreads();
#pragma unroll
    for (int o = 128; o > 0; o >>= 1) {
        if (t < o) red[t] += red[t + o];
        __syncthreads();
    }
    const float mu = red[0] * (1.f / 1024.f);
    __syncthreads();
    float q = 0.f;
#pragma unroll
    for (int i = 0; i < 4; i++) {
        float d = v[i] - mu;
        q += d * d;
    }
    red[t] = q;
    __syncthreads();
#pragma unroll
    for (int o = 128; o > 0; o >>= 1) {
        if (t < o) red[t] += red[t + o];
        __syncthreads();
    }
    const float rstd = rsqrtf(red[0] * (1.f / 1024.f) + 1e-5f);
    float* hr = h + (size_t)row * 1024;
#pragma unroll
    for (int i = 0; i < 4; i++) {
        const int c = t + i * 256;
        const float hv = (v[i] - mu) * rstd * g[c] + b[c];
        hr[c] = hv;
        if (DO_SPLIT) {
            const size_t o = (size_t)row * 1024 + c;
            __nv_bfloat16 hb = __float2bfloat16(hv);
            hhi[o] = hb;
            hlo[o] = __float2bfloat16(hv - __bfloat162float(hb));
        }
    }
}

// ---------------- head: out[B,10] = h @ wf^T + bf ----------------
__global__ void head_kernel(const float* __restrict__ h, const float* __restrict__ wf,
                            const float* __restrict__ bf, float* __restrict__ out) {
    __shared__ float sh[1024];
    const int row = blockIdx.x;
    const int t = threadIdx.x;
    const float* hr = h + (size_t)row * 1024;
    for (int i = t; i < 1024; i += 256) sh[i] = hr[i];
    __syncthreads();
    const int w = t >> 5;
    const int lane = t & 31;
    for (int j = w; j < OUT_SZ; j += 8) {
        const float* wr = wf + (size_t)j * 1024;
        float s = 0.f;
#pragma unroll 8
        for (int d = lane; d < 1024; d += 32) s += sh[d] * wr[d];
#pragma unroll
        for (int o = 16; o > 0; o >>= 1) s += __shfl_xor_sync(0xffffffffu, s, o);
        if (lane == 0) out[(size_t)row * OUT_SZ + j] = s + bf[j];
    }
}

// ---------------- host orchestration ----------------
struct Bufs {
    __nv_bfloat16 *x_hi, *x_lo, *i_hi, *i_lo;
    float *R, *y, *h;
};

template <int LN_SPLIT>
static void run_block(const float* xin, const __nv_bfloat16* wr_hi, const __nv_bfloat16* wr_lo,
                      const float* br, const __nv_bfloat16* wl_hi, const __nv_bfloat16* wl_lo,
                      const float* bl, const __nv_bfloat16* we_hi, const __nv_bfloat16* we_lo,
                      const float* be, const float* g, const float* b, const Bufs& u) {
    gemm_mma<0><<<dim3(HR_SZ / 64, B_SZ / 128), 256, SMEM_TOTAL>>>(
        u.x_hi, u.x_lo, wr_hi, wr_lo, br, nullptr, u.R, nullptr, nullptr, B_SZ, HR_SZ, D_SZ);
    gemm_mma<3><<<dim3(HR_SZ / 64, B_SZ / 128), 256, SMEM_TOTAL>>>(
        u.x_hi, u.x_lo, wl_hi, wl_lo, bl, u.R, nullptr, u.i_hi, u.i_lo, B_SZ, HR_SZ, D_SZ);
    gemm_mma<2><<<dim3(D_SZ / 64, B_SZ / 128), 256, SMEM_TOTAL>>>(
        u.i_hi, u.i_lo, we_hi, we_lo, be, xin, u.y, nullptr, nullptr, B_SZ, D_SZ, HR_SZ);
    // h = LN(y)*g + b; block 1 also writes the split for block 2's A operand
    ln_kernel<LN_SPLIT><<<B_SZ, 256>>>(u.y, g, b, u.h, u.x_hi, u.x_lo);
}

extern "C" void kernel_launch(void* const* d_in, const int* in_sizes, int n_in, void* d_out,
                              int out_size) {
    (void)in_sizes; (void)n_in; (void)out_size;
    const float* x   = (const float*)d_in[0];
    const float* wr1 = (const float*)d_in[1];
    const float* br1 = (const float*)d_in[2];
    const float* wl1 = (const float*)d_in[3];
    const float* bl1 = (const float*)d_in[4];
    const float* we1 = (const float*)d_in[5];
    const float* be1 = (const float*)d_in[6];
    const float* g1  = (const float*)d_in[7];
    const float* b1  = (const float*)d_in[8];
    const float* wr2 = (const float*)d_in[9];
    const float* br2 = (const float*)d_in[10];
    const float* wl2 = (const float*)d_in[11];
    const float* bl2 = (const float*)d_in[12];
    const float* we2 = (const float*)d_in[13];
    const float* be2 = (const float*)d_in[14];
    const float* g2  = (const float*)d_in[15];
    const float* b2  = (const float*)d_in[16];
    const float* wf  = (const float*)d_in[17];
    const float* bf  = (const float*)d_in[18];
    float* out = (float*)d_out;

    void* pv;
    Bufs u;
    cudaGetSymbolAddress(&pv, g_x_hi); u.x_hi = (__nv_bfloat16*)pv;
    cudaGetSymbolAddress(&pv, g_x_lo); u.x_lo = (__nv_bfloat16*)pv;
    cudaGetSymbolAddress(&pv, g_i_hi); u.i_hi = (__nv_bfloat16*)pv;
    cudaGetSymbolAddress(&pv, g_i_lo); u.i_lo = (__nv_bfloat16*)pv;
    cudaGetSymbolAddress(&pv, g_R);    u.R = (float*)pv;
    cudaGetSymbolAddress(&pv, g_y);    u.y = (float*)pv;
    cudaGetSymbolAddress(&pv, g_h);    u.h = (float*)pv;

    __nv_bfloat16 *wr1h, *wr1l, *wl1h, *wl1l, *we1h, *we1l;
    __nv_bfloat16 *wr2h, *wr2l, *wl2h, *wl2l, *we2h, *we2l;
    cudaGetSymbolAddress(&pv, g_wr1_hi); wr1h = (__nv_bfloat16*)pv;
    cudaGetSymbolAddress(&pv, g_wr1_lo); wr1l = (__nv_bfloat16*)pv;
    cudaGetSymbolAddress(&pv, g_wl1_hi); wl1h = (__nv_bfloat16*)pv;
    cudaGetSymbolAddress(&pv, g_wl1_lo); wl1l = (__nv_bfloat16*)pv;
    cudaGetSymbolAddress(&pv, g_we1_hi); we1h = (__nv_bfloat16*)pv;
    cudaGetSymbolAddress(&pv, g_we1_lo); we1l = (__nv_bfloat16*)pv;
    cudaGetSymbolAddress(&pv, g_wr2_hi); wr2h = (__nv_bfloat16*)pv;
    cudaGetSymbolAddress(&pv, g_wr2_lo); wr2l = (__nv_bfloat16*)pv;
    cudaGetSymbolAddress(&pv, g_wl2_hi); wl2h = (__nv_bfloat16*)pv;
    cudaGetSymbolAddress(&pv, g_wl2_lo); wl2l = (__nv_bfloat16*)pv;
    cudaGetSymbolAddress(&pv, g_we2_hi); we2h = (__nv_bfloat16*)pv;
    cudaGetSymbolAddress(&pv, g_we2_lo); we2l = (__nv_bfloat16*)pv;

    cudaFuncSetAttribute(gemm_mma<0>, cudaFuncAttributeMaxDynamicSharedMemorySize, SMEM_TOTAL);
    cudaFuncSetAttribute(gemm_mma<2>, cudaFuncAttributeMaxDynamicSharedMemorySize, SMEM_TOTAL);
    cudaFuncSetAttribute(gemm_mma<3>, cudaFuncAttributeMaxDynamicSharedMemorySize, SMEM_TOTAL);

    // idx 0 = megasplit, idx 1..3 = GEMMs (ncu -s 5 lands on a GEMM for any 2-4 launch prefix).
    megasplit_kernel<<<B_SZ + 6 * (HR_SZ * D_SZ / 1024), 256>>>(
        x, wr1, wl1, we1, wr2, wl2, we2,
        u.x_hi, u.x_lo, wr1h, wr1l, wl1h, wl1l, we1h, we1l,
        wr2h, wr2l, wl2h, wl2l, we2h, we2l);                                     // 0

    run_block<1>(x, wr1h, wr1l, br1, wl1h, wl1l, bl1, we1h, we1l, be1, g1, b1, u);  // 1..4 (ln writes split)

    run_block<0>(u.h, wr2h, wr2l, br2, wl2h, wl2l, bl2, we2h, we2l, be2, g2, b2, u); // 5..8

    head_kernel<<<B_SZ, 256>>>(u.h, wf, bf, out);                                    // 9
}